// round 14
// baseline (speedup 1.0000x reference)
#include <cuda_runtime.h>
#include <cuda_fp16.h>
#include <cstdint>
#include <cstddef>

#define DIM    1024
#define ALPHA  64
#define NROWS  32768
#define SCALE  0.03125f        // 1/sqrt(1024)
#define TILE_ROWS 128
#define NCTA   (NROWS / TILE_ROWS)

// operand pre-scales (powers of 2, folded out exactly)
#define MT_S   256.0f
#define INV_MT (1.0f / 256.0f)
#define A_S    1024.0f
#define CV_S   64.0f
#define OUT_S  (1.0f / (1024.0f * 64.0f))

// smem layout (bytes), aliased by lifetime:
//   phase1: xs[2][128][72]h @0 (36864), mts[2][64][72]h @36864 (18432)
//   phase2: ls[128][68]f @0 (34816)           [xs dead]
//   A hi:   ahs[128][72]h @55296 (18432)      [alive thru phase3]
//   phase3: cvs[2][64][72]h @73728 (18432)    [dedicated — prefetch pre-softmax]
#define XS_OFF   0
#define MTS_OFF  36864
#define LS_OFF   0
#define AH_OFF   55296
#define CVS_OFF  73728
#define BIAS_OFF 92160
#define SMEM_BYTES 92416

#define KSPLIT 32
__device__ float  g_part[KSPLIT * ALPHA * DIM];
__device__ float  g_bias[ALPHA];
__device__ __half g_Mth[ALPHA * DIM];           // Mt[a][d] * 256
__device__ __half g_CVh[DIM * ALPHA];           // C_V[d][a]*64

// ---------------- helpers ----------------
__device__ __forceinline__ uint32_t fpack(float a, float b) {
    __half2 h = __floats2half2_rn(a, b);
    return *reinterpret_cast<uint32_t*>(&h);
}
__device__ __forceinline__ void mma16816(float* c, const uint32_t* a, const uint32_t* b) {
    asm volatile("mma.sync.aligned.m16n8k16.row.col.f32.f16.f16.f32 "
        "{%0,%1,%2,%3}, {%4,%5,%6,%7}, {%8,%9}, {%0,%1,%2,%3};"
        : "+f"(c[0]), "+f"(c[1]), "+f"(c[2]), "+f"(c[3])
        : "r"(a[0]), "r"(a[1]), "r"(a[2]), "r"(a[3]), "r"(b[0]), "r"(b[1]));
}
__device__ __forceinline__ void ldsm_x4(uint32_t* r, const __half* p) {
    uint32_t a = (uint32_t)__cvta_generic_to_shared(p);
    asm volatile("ldmatrix.sync.aligned.m8n8.x4.shared.b16 {%0,%1,%2,%3}, [%4];"
        : "=r"(r[0]), "=r"(r[1]), "=r"(r[2]), "=r"(r[3]) : "r"(a));
}
__device__ __forceinline__ void cp_async16(void* dst, const void* src) {
    uint32_t s = (uint32_t)__cvta_generic_to_shared(dst);
    asm volatile("cp.async.cg.shared.global [%0], [%1], 16;" :: "r"(s), "l"(src));
}
#define CP_COMMIT() asm volatile("cp.async.commit_group;" ::: "memory")
#define CP_WAIT0()  asm volatile("cp.async.wait_group 0;" ::: "memory")

// ---------------- prep: partial GEMM  Mt_part = C_K^T @ W_Q (K-split 32x32) ----------------
__global__ __launch_bounds__(256) void prep_partial(
    const float* __restrict__ W_Q, const float* __restrict__ C_K)
{
    __shared__ float ck_s[32][68];
    __shared__ float wq_s[32][68];
    const int tid = threadIdx.x;
    const int nb = blockIdx.x & 15, kb = blockIdx.x >> 4;
    const int e0 = kb * 32, d0 = nb * 64;
    #pragma unroll
    for (int j = 0; j < 2; j++) {
        const int v = tid + 256 * j;
        const int e = v >> 4, q = v & 15;
        *(float4*)&ck_s[e][q * 4] = *(const float4*)&C_K[(e0 + e) * ALPHA + q * 4];
        *(float4*)&wq_s[e][q * 4] = *(const float4*)&W_Q[(size_t)(e0 + e) * DIM + d0 + q * 4];
    }
    __syncthreads();
    const int tx = tid & 15, ty = tid >> 4;
    float acc[4][4] = {};
    #pragma unroll 8
    for (int e = 0; e < 32; e++) {
        const float4 av = *(const float4*)&ck_s[e][ty * 4];
        const float4 bv = *(const float4*)&wq_s[e][tx * 4];
        const float aa[4] = {av.x, av.y, av.z, av.w};
        const float bb[4] = {bv.x, bv.y, bv.z, bv.w};
        #pragma unroll
        for (int i = 0; i < 4; i++)
            #pragma unroll
            for (int j = 0; j < 4; j++) acc[i][j] += aa[i] * bb[j];
    }
    #pragma unroll
    for (int i = 0; i < 4; i++) {
        float4 w; w.x = acc[i][0]; w.y = acc[i][1]; w.z = acc[i][2]; w.w = acc[i][3];
        *(float4*)&g_part[kb * (ALPHA * DIM) + (ty * 4 + i) * DIM + d0 + tx * 4] = w;
    }
}

// ---------------- prep: reduce + convert ----------------
__global__ __launch_bounds__(256) void prep_reduce(
    const float* __restrict__ b_Q, const float* __restrict__ C_K,
    const float* __restrict__ C_V)
{
    __shared__ float red[256];
    const int tid = threadIdx.x;
    if (blockIdx.x == 256) {                         // bias block
        const int a = tid & 63, ks = tid >> 6;
        float s = 0.f;
        for (int e = ks * 256; e < ks * 256 + 256; e++)
            s += b_Q[e] * C_K[e * ALPHA + a];
        red[tid] = s;
        __syncthreads();
        if (tid < 64)
            g_bias[tid] = (red[tid] + red[tid + 64] + red[tid + 128] + red[tid + 192]) * SCALE;
        return;
    }
    const int o = blockIdx.x * 256 + tid;
    float s = 0.f;
    #pragma unroll
    for (int p = 0; p < KSPLIT; p++) s += g_part[p * (ALPHA * DIM) + o];
    g_Mth[o] = __float2half_rn(s * SCALE * MT_S);
    g_CVh[o] = __float2half_rn(C_V[o] * CV_S);
}

// ---------------- fused: 1 CTA = 128 rows, 256 threads, 2 CTAs/SM ----------------
__global__ __launch_bounds__(256, 2) void fused_mma(
    const float* __restrict__ x, const int* __restrict__ mask,
    float* __restrict__ out)
{
    extern __shared__ __align__(16) char sm[];
    __half* xs  = (__half*)(sm + XS_OFF);            // 2 bufs of 128*72
    __half* mts = (__half*)(sm + MTS_OFF);           // 2 bufs of 64*72
    float*  ls  = (float*)(sm + LS_OFF);
    __half* ahs = (__half*)(sm + AH_OFF);
    __half* cvs = (__half*)(sm + CVS_OFF);           // 2 bufs of 64*72 (dedicated)
    float*  bsm = (float*)(sm + BIAS_OFF);

    const int tid  = threadIdx.x;
    const int lane = tid & 31, wid = tid >> 5;
    const int gid  = lane >> 2, tig = lane & 3;
    const int rg   = wid >> 1, ng = wid & 1;
    const int row0 = blockIdx.x * TILE_ROWS;

    if (tid < ALPHA) bsm[tid] = g_bias[tid];

    // ldmatrix per-lane coords
    const int arow = rg * 32 + (lane & 15);
    const int acol = (lane >> 4) * 8;
    const int brow = ng * 32 + (lane & 7) + ((lane >> 4) & 1) * 8;
    const int bcol = ((lane >> 3) & 1) * 8;

    // x loader coords
    const int lrow = tid >> 1, lk0 = (tid & 1) * 32;
    // cp.async tile coords: each thread copies 2 consecutive 16B units
    const int trow = (tid * 2) >> 3, tseg = (tid * 2) & 7;   // tseg in {0,2,4,6}

    float4 xv[8];

    auto ldg_x = [&](int c) {
        const float* xp = x + (size_t)(row0 + lrow) * DIM + c * 64 + lk0;
        #pragma unroll
        for (int j = 0; j < 8; j++) xv[j] = *(const float4*)(xp + j * 4);
    };
    auto sts_x = [&](int b) {
        uint32_t hp[16];
        #pragma unroll
        for (int j = 0; j < 8; j++) {
            hp[2 * j]     = fpack(xv[j].x, xv[j].y);
            hp[2 * j + 1] = fpack(xv[j].z, xv[j].w);
        }
        uint4* xd = (uint4*)(xs + b * (128 * 72) + lrow * 72 + lk0);
        #pragma unroll
        for (int q = 0; q < 4; q++)
            xd[q] = make_uint4(hp[4 * q], hp[4 * q + 1], hp[4 * q + 2], hp[4 * q + 3]);
    };
    auto cp_mt = [&](int c, int b) {
        char* dst = (char*)mts + b * 9216 + trow * 144 + tseg * 16;
        const char* src = (const char*)g_Mth + trow * 2048 + c * 128 + tseg * 16;
        cp_async16(dst, src);
        cp_async16(dst + 16, src + 16);          // tseg even -> tseg+1 stays in-row
    };
    auto cp_cv = [&](int c, int b) {
        char* dst = (char*)cvs + b * 9216 + trow * 144 + tseg * 16;
        const char* src = (const char*)g_CVh + (size_t)(c * 64 + trow) * 128 + tseg * 16;
        cp_async16(dst, src);
        cp_async16(dst + 16, src + 16);
    };

    // ---- phase 1: logits = x @ Mt^T, 16 chunks of k=64 ----
    float acc1[2][4][4] = {};
    ldg_x(0);
    cp_mt(0, 0); CP_COMMIT();
    cp_mt(1, 1); CP_COMMIT();
    sts_x(0);
    ldg_x(1);
    CP_WAIT0();
    __syncthreads();
    for (int c = 0; c < 16; c++) {
        const __half* xb  = xs + (c & 1) * (128 * 72);
        const __half* mbf = mts + (c & 1) * (64 * 72);
        #pragma unroll
        for (int ks = 0; ks < 4; ks++) {
            uint32_t A0[2][4], B0[2][4];
            #pragma unroll
            for (int m = 0; m < 2; m++)
                ldsm_x4(A0[m], xb + (arow + m * 16) * 72 + ks * 16 + acol);
            #pragma unroll
            for (int nt = 0; nt < 2; nt++)
                ldsm_x4(B0[nt], mbf + (brow + nt * 16) * 72 + ks * 16 + bcol);
            #pragma unroll
            for (int nt = 0; nt < 2; nt++)
                #pragma unroll
                for (int m = 0; m < 2; m++) {
                    mma16816(acc1[m][nt * 2],     A0[m], &B0[nt][0]);
                    mma16816(acc1[m][nt * 2 + 1], A0[m], &B0[nt][2]);
                }
        }
        if (c < 15) sts_x((c + 1) & 1);
        CP_WAIT0();
        __syncthreads();
        if (c < 14) {
            cp_mt(c + 2, c & 1); CP_COMMIT();
            ldg_x(c + 2);
        }
    }

    // prefetch C_V chunks 0,1 (lands during softmax)
    cp_cv(0, 0); CP_COMMIT();
    cp_cv(1, 1); CP_COMMIT();

    // stash logits to ls (aliases xs; last sync covers mma(15))
    #pragma unroll
    for (int m = 0; m < 2; m++)
        #pragma unroll
        for (int n = 0; n < 4; n++) {
            const int r = rg * 32 + m * 16 + gid;
            const int cc = ng * 32 + n * 8 + tig * 2;
            float* p = ls + r * 68 + cc;
            p[0] = acc1[m][n][0];
            p[1] = acc1[m][n][1];
            p[8 * 68] = acc1[m][n][2];
            p[8 * 68 + 1] = acc1[m][n][3];
        }
    __syncthreads();

    // ---- phase 2: softmax * mask, emit A fp16 (x A_S) ----
    if (tid < TILE_ROWS) {
        float e[64];
        const float* lp = ls + tid * 68;
        float mx = -1e30f;
        #pragma unroll
        for (int a = 0; a < 64; a++) {
            const float v = lp[a] * INV_MT + bsm[a];
            e[a] = v;
            mx = fmaxf(mx, v);
        }
        float s = 0.f;
        #pragma unroll
        for (int a = 0; a < 64; a++) { e[a] = __expf(e[a] - mx); s += e[a]; }
        const float inv = (mask[row0 + tid] ? A_S : 0.0f) / s;
        __half* ahp = ahs + tid * 72;
        #pragma unroll
        for (int a = 0; a < 64; a++)
            ahp[a] = __float2half_rn(e[a] * inv);
    }
    CP_WAIT0();
    __syncthreads();        // ahs ready; cv(0),cv(1) visible

    // ---- phase 3: out = A @ C_V^T, 16 chunks of 64 d ----
    uint32_t Ah[2][4][4];
    #pragma unroll
    for (int m = 0; m < 2; m++)
        #pragma unroll
        for (int ks = 0; ks < 4; ks++)
            ldsm_x4(Ah[m][ks], ahs + (arow + m * 16) * 72 + ks * 16 + acol);

    for (int c = 0; c < 16; c++) {
        const __half* ch = cvs + (c & 1) * (64 * 72);
        float acc[2][4][4] = {};
        #pragma unroll
        for (int ks = 0; ks < 4; ks++) {
            uint32_t Bh[2][4];
            #pragma unroll
            for (int nt = 0; nt < 2; nt++)
                ldsm_x4(Bh[nt], ch + (brow + nt * 16) * 72 + ks * 16 + bcol);
            #pragma unroll
            for (int nt = 0; nt < 2; nt++)
                #pragma unroll
                for (int m = 0; m < 2; m++) {
                    mma16816(acc[m][nt * 2],     Ah[m][ks], &Bh[nt][0]);
                    mma16816(acc[m][nt * 2 + 1], Ah[m][ks], &Bh[nt][2]);
                }
        }
        #pragma unroll
        for (int m = 0; m < 2; m++)
            #pragma unroll
            for (int n = 0; n < 4; n++) {
                const size_t r = (size_t)(row0 + rg * 32 + m * 16 + gid);
                const int d = c * 64 + ng * 32 + n * 8 + tig * 2;
                float* po = out + r * DIM + d;
                po[0] = acc[m][n][0] * OUT_S;
                po[1] = acc[m][n][1] * OUT_S;
                po[8 * DIM] = acc[m][n][2] * OUT_S;
                po[8 * DIM + 1] = acc[m][n][3] * OUT_S;
            }
        CP_WAIT0();
        __syncthreads();
        if (c < 14) { cp_cv(c + 2, c & 1); CP_COMMIT(); }
    }
}

// ---------------------------------------------------------------------------
extern "C" void kernel_launch(void* const* d_in, const int* in_sizes, int n_in,
                              void* d_out, int out_size)
{
    const float* x    = (const float*)d_in[0];
    const int*   mask = (const int*)d_in[1];
    const float* W_Q  = (const float*)d_in[2];
    const float* b_Q  = (const float*)d_in[3];
    const float* C_K  = (const float*)d_in[4];
    const float* C_V  = (const float*)d_in[5];
    float*       out  = (float*)d_out;

    cudaFuncSetAttribute(fused_mma, cudaFuncAttributeMaxDynamicSharedMemorySize, SMEM_BYTES);
    prep_partial<<<KSPLIT * 16, 256>>>(W_Q, C_K);
    prep_reduce<<<257, 256>>>(b_Q, C_K, C_V);
    fused_mma<<<NCTA, 256, SMEM_BYTES>>>(x, mask, out);
}

// round 16
// speedup vs baseline: 1.1668x; 1.1668x over previous
#include <cuda_runtime.h>
#include <cuda_fp16.h>
#include <cstdint>
#include <cstddef>

#define DIM    1024
#define ALPHA  64
#define NROWS  32768
#define SCALE  0.03125f        // 1/sqrt(1024)
#define TILE_ROWS 128
#define NCTA   (NROWS / TILE_ROWS)

// operand pre-scales (powers of 2, folded out exactly)
#define MT_S   256.0f
#define INV_MT (1.0f / 256.0f)
#define A_S    1024.0f
#define CV_S   64.0f
#define OUT_S  (1.0f / (1024.0f * 64.0f))

// smem layout (bytes), aliased by lifetime:
//   phase1: xs[2][128][72]h @0 (36864), mts[2][64][72]h @36864 (18432)
//   phase2: ls[128][68]f @0 (34816)           [xs dead]
//   A hi:   ahs[128][72]h @55296 (18432)      [alive thru phase3]
//   phase3: cvs[2][64][72]h @73728 (18432)    [dedicated — prefetch pre-softmax]
#define XS_OFF   0
#define MTS_OFF  36864
#define LS_OFF   0
#define AH_OFF   55296
#define CVS_OFF  73728
#define BIAS_OFF 92160
#define SMEM_BYTES 92416

#define KSPLIT 32
__device__ float  g_part[KSPLIT * ALPHA * DIM];
__device__ float  g_bias[ALPHA];
__device__ __half g_Mth[ALPHA * DIM];           // Mt[a][d] * 256
__device__ __half g_CVh[DIM * ALPHA];           // C_V[d][a]*64

// ---------------- helpers ----------------
__device__ __forceinline__ uint32_t fpack(float a, float b) {
    __half2 h = __floats2half2_rn(a, b);
    return *reinterpret_cast<uint32_t*>(&h);
}
__device__ __forceinline__ void mma16816(float* c, const uint32_t* a, const uint32_t* b) {
    asm volatile("mma.sync.aligned.m16n8k16.row.col.f32.f16.f16.f32 "
        "{%0,%1,%2,%3}, {%4,%5,%6,%7}, {%8,%9}, {%0,%1,%2,%3};"
        : "+f"(c[0]), "+f"(c[1]), "+f"(c[2]), "+f"(c[3])
        : "r"(a[0]), "r"(a[1]), "r"(a[2]), "r"(a[3]), "r"(b[0]), "r"(b[1]));
}
__device__ __forceinline__ void ldsm_x4(uint32_t* r, const __half* p) {
    uint32_t a = (uint32_t)__cvta_generic_to_shared(p);
    asm volatile("ldmatrix.sync.aligned.m8n8.x4.shared.b16 {%0,%1,%2,%3}, [%4];"
        : "=r"(r[0]), "=r"(r[1]), "=r"(r[2]), "=r"(r[3]) : "r"(a));
}
__device__ __forceinline__ void cp_async16(void* dst, const void* src) {
    uint32_t s = (uint32_t)__cvta_generic_to_shared(dst);
    asm volatile("cp.async.cg.shared.global [%0], [%1], 16;" :: "r"(s), "l"(src));
}
#define CP_COMMIT() asm volatile("cp.async.commit_group;" ::: "memory")
#define CP_WAIT0()  asm volatile("cp.async.wait_group 0;" ::: "memory")

// ---------------- prep: partial GEMM  Mt_part = C_K^T @ W_Q (K-split 32x32) ----------------
__global__ __launch_bounds__(256) void prep_partial(
    const float* __restrict__ W_Q, const float* __restrict__ C_K)
{
    __shared__ float ck_s[32][68];
    __shared__ float wq_s[32][68];
    const int tid = threadIdx.x;
    const int nb = blockIdx.x & 15, kb = blockIdx.x >> 4;
    const int e0 = kb * 32, d0 = nb * 64;
    #pragma unroll
    for (int j = 0; j < 2; j++) {
        const int v = tid + 256 * j;
        const int e = v >> 4, q = v & 15;
        *(float4*)&ck_s[e][q * 4] = *(const float4*)&C_K[(e0 + e) * ALPHA + q * 4];
        *(float4*)&wq_s[e][q * 4] = *(const float4*)&W_Q[(size_t)(e0 + e) * DIM + d0 + q * 4];
    }
    __syncthreads();
    const int tx = tid & 15, ty = tid >> 4;
    float acc[4][4] = {};
    #pragma unroll 8
    for (int e = 0; e < 32; e++) {
        const float4 av = *(const float4*)&ck_s[e][ty * 4];
        const float4 bv = *(const float4*)&wq_s[e][tx * 4];
        const float aa[4] = {av.x, av.y, av.z, av.w};
        const float bb[4] = {bv.x, bv.y, bv.z, bv.w};
        #pragma unroll
        for (int i = 0; i < 4; i++)
            #pragma unroll
            for (int j = 0; j < 4; j++) acc[i][j] += aa[i] * bb[j];
    }
    #pragma unroll
    for (int i = 0; i < 4; i++) {
        float4 w; w.x = acc[i][0]; w.y = acc[i][1]; w.z = acc[i][2]; w.w = acc[i][3];
        *(float4*)&g_part[kb * (ALPHA * DIM) + (ty * 4 + i) * DIM + d0 + tx * 4] = w;
    }
}

// ---------------- prep: reduce + convert ----------------
__global__ __launch_bounds__(256) void prep_reduce(
    const float* __restrict__ b_Q, const float* __restrict__ C_K,
    const float* __restrict__ C_V)
{
    __shared__ float red[256];
    const int tid = threadIdx.x;
    if (blockIdx.x == 256) {                         // bias block
        const int a = tid & 63, ks = tid >> 6;
        float s = 0.f;
        for (int e = ks * 256; e < ks * 256 + 256; e++)
            s += b_Q[e] * C_K[e * ALPHA + a];
        red[tid] = s;
        __syncthreads();
        if (tid < 64)
            g_bias[tid] = (red[tid] + red[tid + 64] + red[tid + 128] + red[tid + 192]) * SCALE;
        return;
    }
    const int o = blockIdx.x * 256 + tid;
    float s = 0.f;
    #pragma unroll
    for (int p = 0; p < KSPLIT; p++) s += g_part[p * (ALPHA * DIM) + o];
    g_Mth[o] = __float2half_rn(s * SCALE * MT_S);
    g_CVh[o] = __float2half_rn(C_V[o] * CV_S);
}

// ---------------- fused: 1 CTA = 128 rows, 256 threads, 2 CTAs/SM ----------------
__global__ __launch_bounds__(256, 2) void fused_mma(
    const float* __restrict__ x, const int* __restrict__ mask,
    float* __restrict__ out)
{
    extern __shared__ __align__(16) char sm[];
    __half* xs  = (__half*)(sm + XS_OFF);            // 2 bufs of 128*72
    __half* mts = (__half*)(sm + MTS_OFF);           // 2 bufs of 64*72
    float*  ls  = (float*)(sm + LS_OFF);
    __half* ahs = (__half*)(sm + AH_OFF);
    __half* cvs = (__half*)(sm + CVS_OFF);           // 2 bufs of 64*72 (dedicated)
    float*  bsm = (float*)(sm + BIAS_OFF);

    const int tid  = threadIdx.x;
    const int lane = tid & 31, wid = tid >> 5;
    const int gid  = lane >> 2, tig = lane & 3;
    const int rg   = wid >> 1, ng = wid & 1;
    const int row0 = blockIdx.x * TILE_ROWS;

    if (tid < ALPHA) bsm[tid] = g_bias[tid];

    // ldmatrix per-lane coords
    const int arow = rg * 32 + (lane & 15);
    const int acol = (lane >> 4) * 8;
    const int brow = ng * 32 + (lane & 7) + ((lane >> 4) & 1) * 8;
    const int bcol = ((lane >> 3) & 1) * 8;

    // x loader coords: warp-contiguous — warp owns 16 rows; per instr,
    // lanes 0-15 cover row's full 64-float chunk, lanes 16-31 the next row.
    const int xrow = wid * 16 + (lane >> 4);         // + i*2
    const int xcol = (lane & 15) * 4;
    // cp.async tile coords: each thread copies 2 consecutive 16B units
    const int trow = (tid * 2) >> 3, tseg = (tid * 2) & 7;   // tseg in {0,2,4,6}

    float4 xv[8];

    auto ldg_x = [&](int c) {
        const float* xp = x + (size_t)(row0 + xrow) * DIM + c * 64 + xcol;
        #pragma unroll
        for (int i = 0; i < 8; i++)
            xv[i] = *(const float4*)(xp + (size_t)(i * 2) * DIM);
    };
    auto sts_x = [&](int b) {
        __half* xd = xs + b * (128 * 72) + xrow * 72 + xcol;
        #pragma unroll
        for (int i = 0; i < 8; i++) {
            uint2 h;
            h.x = fpack(xv[i].x, xv[i].y);
            h.y = fpack(xv[i].z, xv[i].w);
            *(uint2*)(xd + i * 2 * 72) = h;
        }
    };
    auto cp_mt = [&](int c, int b) {
        char* dst = (char*)mts + b * 9216 + trow * 144 + tseg * 16;
        const char* src = (const char*)g_Mth + trow * 2048 + c * 128 + tseg * 16;
        cp_async16(dst, src);
        cp_async16(dst + 16, src + 16);          // tseg even -> tseg+1 stays in-row
    };
    auto cp_cv = [&](int c, int b) {
        char* dst = (char*)cvs + b * 9216 + trow * 144 + tseg * 16;
        const char* src = (const char*)g_CVh + (size_t)(c * 64 + trow) * 128 + tseg * 16;
        cp_async16(dst, src);
        cp_async16(dst + 16, src + 16);
    };

    // ---- phase 1: logits = x @ Mt^T, 16 chunks of k=64 ----
    float acc1[2][4][4] = {};
    ldg_x(0);
    cp_mt(0, 0); CP_COMMIT();
    cp_mt(1, 1); CP_COMMIT();
    sts_x(0);
    ldg_x(1);
    CP_WAIT0();
    __syncthreads();
    for (int c = 0; c < 16; c++) {
        const __half* xb  = xs + (c & 1) * (128 * 72);
        const __half* mbf = mts + (c & 1) * (64 * 72);
        #pragma unroll
        for (int ks = 0; ks < 4; ks++) {
            uint32_t A0[2][4], B0[2][4];
            #pragma unroll
            for (int m = 0; m < 2; m++)
                ldsm_x4(A0[m], xb + (arow + m * 16) * 72 + ks * 16 + acol);
            #pragma unroll
            for (int nt = 0; nt < 2; nt++)
                ldsm_x4(B0[nt], mbf + (brow + nt * 16) * 72 + ks * 16 + bcol);
            #pragma unroll
            for (int nt = 0; nt < 2; nt++)
                #pragma unroll
                for (int m = 0; m < 2; m++) {
                    mma16816(acc1[m][nt * 2],     A0[m], &B0[nt][0]);
                    mma16816(acc1[m][nt * 2 + 1], A0[m], &B0[nt][2]);
                }
        }
        if (c < 15) sts_x((c + 1) & 1);
        CP_WAIT0();
        __syncthreads();
        if (c < 14) {
            cp_mt(c + 2, c & 1); CP_COMMIT();
            ldg_x(c + 2);
        }
    }

    // prefetch C_V chunks 0,1 (lands during softmax)
    cp_cv(0, 0); CP_COMMIT();
    cp_cv(1, 1); CP_COMMIT();

    // stash logits to ls (aliases xs; last sync covers mma(15))
    #pragma unroll
    for (int m = 0; m < 2; m++)
        #pragma unroll
        for (int n = 0; n < 4; n++) {
            const int r = rg * 32 + m * 16 + gid;
            const int cc = ng * 32 + n * 8 + tig * 2;
            float* p = ls + r * 68 + cc;
            p[0] = acc1[m][n][0];
            p[1] = acc1[m][n][1];
            p[8 * 68] = acc1[m][n][2];
            p[8 * 68 + 1] = acc1[m][n][3];
        }
    __syncthreads();

    // ---- phase 2: softmax * mask, emit A fp16 (x A_S) ----
    if (tid < TILE_ROWS) {
        float e[64];
        const float* lp = ls + tid * 68;
        float mx = -1e30f;
        #pragma unroll
        for (int a = 0; a < 64; a++) {
            const float v = lp[a] * INV_MT + bsm[a];
            e[a] = v;
            mx = fmaxf(mx, v);
        }
        float s = 0.f;
        #pragma unroll
        for (int a = 0; a < 64; a++) { e[a] = __expf(e[a] - mx); s += e[a]; }
        const float inv = (mask[row0 + tid] ? A_S : 0.0f) / s;
        __half* ahp = ahs + tid * 72;
        #pragma unroll
        for (int a = 0; a < 64; a++)
            ahp[a] = __float2half_rn(e[a] * inv);
    }
    CP_WAIT0();
    __syncthreads();        // ahs ready; cv(0),cv(1) visible

    // ---- phase 3: out = A @ C_V^T, 16 chunks of 64 d ----
    uint32_t Ah[2][4][4];
    #pragma unroll
    for (int m = 0; m < 2; m++)
        #pragma unroll
        for (int ks = 0; ks < 4; ks++)
            ldsm_x4(Ah[m][ks], ahs + (arow + m * 16) * 72 + ks * 16 + acol);

    for (int c = 0; c < 16; c++) {
        const __half* ch = cvs + (c & 1) * (64 * 72);
        float acc[2][4][4] = {};
        #pragma unroll
        for (int ks = 0; ks < 4; ks++) {
            uint32_t Bh[2][4];
            #pragma unroll
            for (int nt = 0; nt < 2; nt++)
                ldsm_x4(Bh[nt], ch + (brow + nt * 16) * 72 + ks * 16 + bcol);
            #pragma unroll
            for (int nt = 0; nt < 2; nt++)
                #pragma unroll
                for (int m = 0; m < 2; m++) {
                    mma16816(acc[m][nt * 2],     Ah[m][ks], &Bh[nt][0]);
                    mma16816(acc[m][nt * 2 + 1], Ah[m][ks], &Bh[nt][2]);
                }
        }
        #pragma unroll
        for (int m = 0; m < 2; m++)
            #pragma unroll
            for (int n = 0; n < 4; n++) {
                const size_t r = (size_t)(row0 + rg * 32 + m * 16 + gid);
                const int d = c * 64 + ng * 32 + n * 8 + tig * 2;
                float* po = out + r * DIM + d;
                po[0] = acc[m][n][0] * OUT_S;
                po[1] = acc[m][n][1] * OUT_S;
                po[8 * DIM] = acc[m][n][2] * OUT_S;
                po[8 * DIM + 1] = acc[m][n][3] * OUT_S;
            }
        CP_WAIT0();
        __syncthreads();
        if (c < 14) { cp_cv(c + 2, c & 1); CP_COMMIT(); }
    }
}

// ---------------------------------------------------------------------------
extern "C" void kernel_launch(void* const* d_in, const int* in_sizes, int n_in,
                              void* d_out, int out_size)
{
    const float* x    = (const float*)d_in[0];
    const int*   mask = (const int*)d_in[1];
    const float* W_Q  = (const float*)d_in[2];
    const float* b_Q  = (const float*)d_in[3];
    const float* C_K  = (const float*)d_in[4];
    const float* C_V  = (const float*)d_in[5];
    float*       out  = (float*)d_out;

    cudaFuncSetAttribute(fused_mma, cudaFuncAttributeMaxDynamicSharedMemorySize, SMEM_BYTES);
    prep_partial<<<KSPLIT * 16, 256>>>(W_Q, C_K);
    prep_reduce<<<257, 256>>>(b_Q, C_K, C_V);
    fused_mma<<<NCTA, 256, SMEM_BYTES>>>(x, mask, out);
}